// round 4
// baseline (speedup 1.0000x reference)
#include <cuda_runtime.h>
#include <cuda_bf16.h>
#include <cstdint>

// Problem constants (fixed by setup_inputs: [32, 3, 512, 512] fp32, BINS=64)
#define BINS        64
#define ROWS        96           // B*C = 32*3
#define HW          262144       // 512*512, elements per row
#define N_ELEM      25165824     // ROWS * HW per image
#define CHUNK       32768        // elements per block
#define CHUNK_V4    8192         // float4 per block
#define BLOCKS_IMG  768          // N_ELEM / CHUNK
#define CHUNKS_ROW  8            // HW / CHUNK
#define THREADS     256
#define WARPS       8

// Scratch: exact integer histograms, [image][row][bin]
__device__ int g_hist[2 * ROWS * BINS];

__global__ void zero_hist_kernel() {
    int i = blockIdx.x * blockDim.x + threadIdx.x;
    if (i < 2 * ROWS * BINS) g_hist[i] = 0;
}

__device__ __forceinline__ int bin_of(float x) {
    // reference: clip(x,0,1) -> (int)(x*64) -> clip(idx,0,63)
    float c = fminf(fmaxf(x, 0.0f), 1.0f);
    return min((int)(c * 64.0f), 63);
}

__global__ __launch_bounds__(THREADS) void hist_kernel(const float* __restrict__ fake,
                                                       const float* __restrict__ real) {
    __shared__ int sh[WARPS * BINS];

    const int tid  = threadIdx.x;
    const int warp = tid >> 5;
    const int img  = blockIdx.y;             // 0 = fake, 1 = real
    const float* __restrict__ src = (img == 0) ? fake : real;

    // zero per-warp sub-histograms
    #pragma unroll
    for (int i = tid; i < WARPS * BINS; i += THREADS) sh[i] = 0;
    __syncthreads();

    const float4* __restrict__ p =
        reinterpret_cast<const float4*>(src) + (size_t)blockIdx.x * CHUNK_V4;

    int* myh = &sh[warp * BINS];

    // 2 float4 per thread per iter -> 16 iters total; loads batched ahead of
    // the atomic chain for MLP.
    #pragma unroll 4
    for (int i = tid; i < CHUNK_V4; i += 2 * THREADS) {
        float4 v0 = __ldcs(&p[i]);
        float4 v1 = __ldcs(&p[i + THREADS]);

        int b0 = bin_of(v0.x), b1 = bin_of(v0.y), b2 = bin_of(v0.z), b3 = bin_of(v0.w);
        int b4 = bin_of(v1.x), b5 = bin_of(v1.y), b6 = bin_of(v1.z), b7 = bin_of(v1.w);

        atomicAdd(&myh[b0], 1);
        atomicAdd(&myh[b1], 1);
        atomicAdd(&myh[b2], 1);
        atomicAdd(&myh[b3], 1);
        atomicAdd(&myh[b4], 1);
        atomicAdd(&myh[b5], 1);
        atomicAdd(&myh[b6], 1);
        atomicAdd(&myh[b7], 1);
    }
    __syncthreads();

    // reduce 8 warp-histograms -> 64 bins, one global atomic per bin
    if (tid < BINS) {
        int s = 0;
        #pragma unroll
        for (int w = 0; w < WARPS; w++) s += sh[w * BINS + tid];
        const int row = blockIdx.x / CHUNKS_ROW;
        atomicAdd(&g_hist[img * (ROWS * BINS) + row * BINS + tid], s);
    }
}

__global__ __launch_bounds__(1024) void loss_kernel(float* __restrict__ out) {
    __shared__ int sh[32];
    const int tid = threadIdx.x;

    int acc = 0;   // max total |diff| = 2*HW*ROWS ~= 5.0e7, fits int
    #pragma unroll
    for (int i = tid; i < ROWS * BINS; i += 1024) {
        int d = g_hist[i] - g_hist[ROWS * BINS + i];
        acc += (d < 0) ? -d : d;
    }

    // warp reduce
    #pragma unroll
    for (int off = 16; off > 0; off >>= 1)
        acc += __shfl_down_sync(0xFFFFFFFFu, acc, off);
    if ((tid & 31) == 0) sh[tid >> 5] = acc;
    __syncthreads();
    if (tid < 32) {
        int v = sh[tid];
        #pragma unroll
        for (int off = 16; off > 0; off >>= 1)
            v += __shfl_down_sync(0xFFFFFFFFu, v, off);
        if (tid == 0) {
            // loss = sum|dcnt| / (ROWS*BINS * HW)
            double scale = 1.0 / ((double)(ROWS * BINS) * (double)HW);
            out[0] = (float)((double)v * scale);
        }
    }
}

extern "C" void kernel_launch(void* const* d_in, const int* in_sizes, int n_in,
                              void* d_out, int out_size) {
    const float* fake = (const float*)d_in[0];
    const float* real = (const float*)d_in[1];
    float* out = (float*)d_out;

    zero_hist_kernel<<<(2 * ROWS * BINS + 255) / 256, 256>>>();
    hist_kernel<<<dim3(BLOCKS_IMG, 2), THREADS>>>(fake, real);
    loss_kernel<<<1, 1024>>>(out);
}

// round 6
// speedup vs baseline: 1.0666x; 1.0666x over previous
#include <cuda_runtime.h>
#include <cuda_bf16.h>
#include <cstdint>

// Problem constants (fixed by setup_inputs: [32, 3, 512, 512] fp32, BINS=64)
#define BINS        64
#define ROWS        96           // B*C = 32*3
#define HW          262144       // 512*512, elements per row
#define CHUNK       16384        // elements per block
#define CHUNK_V4    4096         // float4 per block
#define BLOCKS_IMG  1536         // (ROWS*HW) / CHUNK
#define CHUNKS_ROW  16           // HW / CHUNK
#define THREADS     256
#define WARPS       8
#define REP         4            // bank-strided replicas per warp hist

// Exact integer histograms, [image][row][bin]. Static-zeroed at module load;
// loss_kernel re-zeros at the end of every invocation so each graph replay
// starts from zero (deterministic).
__device__ int g_hist[2 * ROWS * BINS];

__device__ __forceinline__ int bin_of(float x) {
    // reference: clip(x,0,1) -> (int)(x*64) -> clip(idx,0,63)
    float c = fminf(fmaxf(x, 0.0f), 1.0f);
    return min((int)(c * 64.0f), 63);
}

__global__ __launch_bounds__(THREADS) void hist_kernel(const float* __restrict__ fake,
                                                       const float* __restrict__ real) {
    // per-warp histogram, 4-way bank-strided: slot = bin*REP + (lane&3)
    __shared__ int sh[WARPS * BINS * REP];

    const int tid  = threadIdx.x;
    const int warp = tid >> 5;
    const int q    = tid & 3;                // bank-group within warp
    const int img  = blockIdx.y;             // 0 = fake, 1 = real
    const float* __restrict__ src = (img == 0) ? fake : real;

    #pragma unroll
    for (int i = tid; i < WARPS * BINS * REP; i += THREADS) sh[i] = 0;
    __syncthreads();

    const float4* __restrict__ p =
        reinterpret_cast<const float4*>(src) + (size_t)blockIdx.x * CHUNK_V4;

    int* myh = &sh[warp * BINS * REP + q];

    // 2 float4 per thread per iter; loads batched ahead of the atomic chain.
    #pragma unroll 4
    for (int i = tid; i < CHUNK_V4; i += 2 * THREADS) {
        float4 v0 = __ldcs(&p[i]);
        float4 v1 = __ldcs(&p[i + THREADS]);

        int b0 = bin_of(v0.x), b1 = bin_of(v0.y), b2 = bin_of(v0.z), b3 = bin_of(v0.w);
        int b4 = bin_of(v1.x), b5 = bin_of(v1.y), b6 = bin_of(v1.z), b7 = bin_of(v1.w);

        atomicAdd(&myh[b0 * REP], 1);
        atomicAdd(&myh[b1 * REP], 1);
        atomicAdd(&myh[b2 * REP], 1);
        atomicAdd(&myh[b3 * REP], 1);
        atomicAdd(&myh[b4 * REP], 1);
        atomicAdd(&myh[b5 * REP], 1);
        atomicAdd(&myh[b6 * REP], 1);
        atomicAdd(&myh[b7 * REP], 1);
    }
    __syncthreads();

    // reduce 8 warps x 4 replicas -> 64 bins, one global atomic per bin
    if (tid < BINS) {
        int s = 0;
        #pragma unroll
        for (int w = 0; w < WARPS; w++) {
            const int* h = &sh[w * BINS * REP + tid * REP];
            s += h[0] + h[1] + h[2] + h[3];
        }
        const int row = blockIdx.x / CHUNKS_ROW;
        atomicAdd(&g_hist[img * (ROWS * BINS) + row * BINS + tid], s);
    }
}

__global__ __launch_bounds__(1024) void loss_kernel(float* __restrict__ out) {
    __shared__ int sh[32];
    const int tid = threadIdx.x;

    int acc = 0;   // max total |diff| = 2*HW*ROWS ~= 5.0e7, fits int
    #pragma unroll
    for (int i = tid; i < ROWS * BINS; i += 1024) {
        int d = g_hist[i] - g_hist[ROWS * BINS + i];
        acc += (d < 0) ? -d : d;
    }

    // warp reduce
    #pragma unroll
    for (int off = 16; off > 0; off >>= 1)
        acc += __shfl_down_sync(0xFFFFFFFFu, acc, off);
    if ((tid & 31) == 0) sh[tid >> 5] = acc;
    __syncthreads();
    if (tid < 32) {
        int v = sh[tid];
        #pragma unroll
        for (int off = 16; off > 0; off >>= 1)
            v += __shfl_down_sync(0xFFFFFFFFu, v, off);
        if (tid == 0) {
            // loss = sum|dcnt| / (ROWS*BINS * HW)
            double scale = 1.0 / ((double)(ROWS * BINS) * (double)HW);
            out[0] = (float)((double)v * scale);
        }
    }

    // Re-zero g_hist for the next replay (all reads above are done:
    // every thread finished its read loop before the warp-reduce; the
    // __syncthreads below orders reads of ALL threads before any write).
    __syncthreads();
    #pragma unroll
    for (int i = tid; i < 2 * ROWS * BINS; i += 1024) g_hist[i] = 0;
}

extern "C" void kernel_launch(void* const* d_in, const int* in_sizes, int n_in,
                              void* d_out, int out_size) {
    const float* fake = (const float*)d_in[0];
    const float* real = (const float*)d_in[1];
    float* out = (float*)d_out;

    hist_kernel<<<dim3(BLOCKS_IMG, 2), THREADS>>>(fake, real);
    loss_kernel<<<1, 1024>>>(out);
}